// round 16
// baseline (speedup 1.0000x reference)
#include <cuda_runtime.h>

// Transducer KD loss prep — 16-deep front-batch: one warp = TWO adjacent
// (n,t,u) positions (4 rows: student+teacher x2) = 4KB in flight per warp.
// logits/teacher (N=8,T=200,U=50,V=500) fp32; y (N,U) i32; x_lens,y_lens (N,) i32.
// Output (2, N, T, U, 3) fp32.
//
// All 16 LDG.128.cs front-batched; every vector is anchored by a shfl-based
// gather extraction (unrematerializable second use) so ptxas must keep the
// full batch live (regs ~84). In-flight bytes/SM ~96KB vs the 62KB plateau
// of the 8-deep versions. Epilogue: lane 0 stores pos0, lane 1 stores pos1.

#define TN 8
#define TT 200
#define TU 50
#define TV 500
#define ROWS (TN * TT * TU)     // 80000
#define PAIRS (ROWS / 2)        // 40000
#define T_EPS 1e-10f
#define NEG_BIG -1e30f

__device__ __forceinline__ float sel_comp(float4 v, int comp) {
    return (comp == 0) ? v.x : (comp == 1) ? v.y : (comp == 2) ? v.z : v.w;
}

__global__ void __launch_bounds__(64)
transducer_kd_kernel(const float* __restrict__ logits,
                     const float* __restrict__ teacher,
                     const int*   __restrict__ y,
                     const int*   __restrict__ x_lens,
                     const int*   __restrict__ y_lens,
                     float*       __restrict__ out)
{
    const int warp_global = (int)((blockIdx.x * blockDim.x + threadIdx.x) >> 5);
    const int lane = threadIdx.x & 31;
    if (warp_global >= PAIRS) return;

    const int r0 = warp_global * 2;
    const int r1 = r0 + 1;

    // decode both positions (same n; u adjacent except at u-boundary)
    const int n0  = r0 / (TT * TU);
    const int tu0 = r0 - n0 * (TT * TU);
    const int t0  = tu0 / TU;
    const int u0  = tu0 - t0 * TU;
    const int n1  = r1 / (TT * TU);
    const int tu1 = r1 - n1 * (TT * TU);
    const int t1  = tu1 / TU;
    const int u1  = tu1 - t1 * TU;

    const bool a0 = (t0 < x_lens[n0]) && (u0 < y_lens[n0]);
    const bool a1 = (t1 < x_lens[n1]) && (u1 < y_lens[n1]);

    float* os0 = out + (size_t)r0 * 3;
    float* ot0 = out + (size_t)(ROWS + r0) * 3;
    float* os1 = out + (size_t)r1 * 3;
    float* ot1 = out + (size_t)(ROWS + r1) * 3;

    if (!a0 && !a1) {
        if (lane < 3) {
            os0[lane] = 0.0f; ot0[lane] = 0.0f;
            os1[lane] = 0.0f; ot1[lane] = 0.0f;
        }
        return;
    }

    const float4* s40 = (const float4*)(logits  + (size_t)r0 * TV);
    const float4* t40 = (const float4*)(teacher + (size_t)r0 * TV);
    const float4* s41 = (const float4*)(logits  + (size_t)r1 * TV);
    const float4* t41 = (const float4*)(teacher + (size_t)r1 * TV);
    const bool tail = (lane < 29);            // 125 float4 per row

    const float4 FILL = make_float4(NEG_BIG, NEG_BIG, NEG_BIG, NEG_BIG);

    // ---- Phase 1: 16 front-batched streaming loads (predicated on act) ----
    float4 s0v0 = FILL, s0v1 = FILL, s0v2 = FILL, s0v3 = FILL;
    float4 t0v0 = FILL, t0v1 = FILL, t0v2 = FILL, t0v3 = FILL;
    float4 s1v0 = FILL, s1v1 = FILL, s1v2 = FILL, s1v3 = FILL;
    float4 t1v0 = FILL, t1v1 = FILL, t1v2 = FILL, t1v3 = FILL;
    if (a0) {
        s0v0 = __ldcs(s40 + lane);
        s0v1 = __ldcs(s40 + lane + 32);
        s0v2 = __ldcs(s40 + lane + 64);
        t0v0 = __ldcs(t40 + lane);
        t0v1 = __ldcs(t40 + lane + 32);
        t0v2 = __ldcs(t40 + lane + 64);
        if (tail) {
            s0v3 = __ldcs(s40 + lane + 96);
            t0v3 = __ldcs(t40 + lane + 96);
        }
    }
    if (a1) {
        s1v0 = __ldcs(s41 + lane);
        s1v1 = __ldcs(s41 + lane + 32);
        s1v2 = __ldcs(s41 + lane + 64);
        t1v0 = __ldcs(t41 + lane);
        t1v1 = __ldcs(t41 + lane + 32);
        t1v2 = __ldcs(t41 + lane + 64);
        if (tail) {
            s1v3 = __ldcs(s41 + lane + 96);
            t1v3 = __ldcs(t41 + lane + 96);
        }
    }

    const int yi0 = __ldg(y + n0 * TU + u0);
    const int yi1 = __ldg(y + n1 * TU + u1);

    // ---- shfl-extract gathered logits (liveness anchor for all 16 vecs) ----
    const int i40 = yi0 >> 2, c0 = yi0 & 3, sr0 = i40 & 31, g0 = i40 >> 5;
    const int i41 = yi1 >> 2, c1 = yi1 & 3, sr1 = i41 & 31, g1 = i41 >> 5;

    float4 sy0 = (g0 == 0) ? s0v0 : (g0 == 1) ? s0v1 : (g0 == 2) ? s0v2 : s0v3;
    float4 ty0 = (g0 == 0) ? t0v0 : (g0 == 1) ? t0v1 : (g0 == 2) ? t0v2 : t0v3;
    float4 sy1 = (g1 == 0) ? s1v0 : (g1 == 1) ? s1v1 : (g1 == 2) ? s1v2 : s1v3;
    float4 ty1 = (g1 == 0) ? t1v0 : (g1 == 1) ? t1v1 : (g1 == 2) ? t1v2 : t1v3;

    const float s_ly0 = __shfl_sync(0xFFFFFFFFu, sel_comp(sy0, c0), sr0);
    const float t_ly0 = __shfl_sync(0xFFFFFFFFu, sel_comp(ty0, c0), sr0);
    const float s_ly1 = __shfl_sync(0xFFFFFFFFu, sel_comp(sy1, c1), sr1);
    const float t_ly1 = __shfl_sync(0xFFFFFFFFu, sel_comp(ty1, c1), sr1);
    const float s_lb0 = __shfl_sync(0xFFFFFFFFu, s0v0.x, 0);
    const float t_lb0 = __shfl_sync(0xFFFFFFFFu, t0v0.x, 0);
    const float s_lb1 = __shfl_sync(0xFFFFFFFFu, s1v0.x, 0);
    const float t_lb1 = __shfl_sync(0xFFFFFFFFu, t1v0.x, 0);

    // ---- Phase 2: exp + tree sums (4 rows) ----
    #define ESUM(v) ((__expf((v).x) + __expf((v).y)) + (__expf((v).z) + __expf((v).w)))
    float sa0 = ESUM(s0v0) + ESUM(s0v1) + ESUM(s0v2) + ESUM(s0v3);
    float ta0 = ESUM(t0v0) + ESUM(t0v1) + ESUM(t0v2) + ESUM(t0v3);
    float sa1 = ESUM(s1v0) + ESUM(s1v1) + ESUM(s1v2) + ESUM(s1v3);
    float ta1 = ESUM(t1v0) + ESUM(t1v1) + ESUM(t1v2) + ESUM(t1v3);
    #undef ESUM

    #pragma unroll
    for (int off = 16; off > 0; off >>= 1) {
        sa0 += __shfl_xor_sync(0xFFFFFFFFu, sa0, off);
        ta0 += __shfl_xor_sync(0xFFFFFFFFu, ta0, off);
        sa1 += __shfl_xor_sync(0xFFFFFFFFu, sa1, off);
        ta1 += __shfl_xor_sync(0xFFFFFFFFu, ta1, off);
    }

    // ---- Epilogue: lane 0 -> pos0, lane 1 -> pos1 ----
    const bool mylane = (lane < 2);
    if (mylane) {
        const bool  act = (lane == 0) ? a0 : a1;
        float* os = (lane == 0) ? os0 : os1;
        float* ot = (lane == 0) ? ot0 : ot1;
        if (!act) {
            os[0] = 0.0f; os[1] = 0.0f; os[2] = 0.0f;
            ot[0] = 0.0f; ot[1] = 0.0f; ot[2] = 0.0f;
        } else {
            const float sa  = (lane == 0) ? sa0  : sa1;
            const float ta  = (lane == 0) ? ta0  : ta1;
            const float sly = (lane == 0) ? s_ly0 : s_ly1;
            const float tly = (lane == 0) ? t_ly0 : t_ly1;
            const float slb = (lane == 0) ? s_lb0 : s_lb1;
            const float tlb = (lane == 0) ? t_lb0 : t_lb1;

            const float sinv   = __fdividef(1.0f, sa);
            const float spy    = __expf(sly) * sinv;
            const float sblank = __expf(slb) * sinv;
            const float srem   = 1.0f - spy - sblank;
            os[0] = __logf(fminf(fmaxf(spy,    T_EPS), 1.0f));
            os[1] = __logf(fminf(fmaxf(sblank, T_EPS), 1.0f));
            os[2] = __logf(fminf(fmaxf(srem,   T_EPS), 1.0f));

            const float tinv   = __fdividef(1.0f, ta);
            const float tpy    = __expf(tly) * tinv;
            const float tblank = __expf(tlb) * tinv;
            const float trem   = 1.0f - tpy - tblank;
            ot[0] = tpy;
            ot[1] = tblank;
            ot[2] = (trem < 0.0f) ? T_EPS : trem;
        }
    }
}

extern "C" void kernel_launch(void* const* d_in, const int* in_sizes, int n_in,
                              void* d_out, int out_size)
{
    const float* logits  = (const float*)d_in[0];
    const float* teacher = (const float*)d_in[1];
    const int*   y       = (const int*)d_in[2];
    const int*   x_lens  = (const int*)d_in[3];
    const int*   y_lens  = (const int*)d_in[4];
    float* out = (float*)d_out;

    const int WARPS_PER_BLOCK = 2;          // 64 threads
    const int blocks = (PAIRS + WARPS_PER_BLOCK - 1) / WARPS_PER_BLOCK;
    transducer_kd_kernel<<<blocks, WARPS_PER_BLOCK * 32>>>(
        logits, teacher, y, x_lens, y_lens, out);
}